// round 4
// baseline (speedup 1.0000x reference)
#include <cuda_runtime.h>
#include <cuda_fp16.h>
#include <stdint.h>

#define B_   32
#define T_   8192
#define DX   256
#define DY   128
#define DU   64
#define DIN  192   // DY + DU
#define DON  192   // DYH(128) + DZH(64)
#define KTAP 16

// ---------------- persistent device scratch (no allocations allowed) ----------------
__device__ float  g_G [KTAP * DON * DX];   // G_j = C * W_A^j   (fp32)
__device__ float  g_Wd[DX * DIN];          // [W_K | W_B]       (fp32)
__device__ float  g_e [(KTAP + 1) * DON];  // bias table e_m, m = 0..16
__device__ __half g_R [KTAP * DON * DIN];  // folded conv weights R_j[n][c] (fp16)

// ---------------- precompute kernels ----------------
__global__ void k_copy_g0(const float* __restrict__ Wcy, const float* __restrict__ Wcz,
                          float* __restrict__ G) {
    int idx = blockIdx.x * 256 + threadIdx.x;
    if (idx >= DON * DX) return;
    int n = idx / DX, i = idx % DX;
    G[idx] = (n < DY) ? Wcy[n * DX + i] : Wcz[(n - DY) * DX + i];
}

__global__ void k_asm_wd(const float* __restrict__ Wk, const float* __restrict__ Wb,
                         float* __restrict__ Wd) {
    int idx = blockIdx.x * 256 + threadIdx.x;
    if (idx >= DX * DIN) return;
    int i = idx / DIN, c = idx % DIN;
    Wd[idx] = (c < DY) ? Wk[i * DY + c] : Wb[i * DU + (c - DY)];
}

// C[M,N] = A[M,256] * B[256,N]  (fp32 row-major, K fixed = DX)
__global__ void k_gemm(const float* __restrict__ A, const float* __restrict__ Bm,
                       float* __restrict__ C, int M, int N) {
    __shared__ float As[16][17], Bs[16][17];
    int tx = threadIdx.x, ty = threadIdx.y;
    int row = blockIdx.y * 16 + ty, col = blockIdx.x * 16 + tx;
    float acc = 0.f;
    for (int k0 = 0; k0 < DX; k0 += 16) {
        As[ty][tx] = (row < M) ? A[row * DX + k0 + tx] : 0.f;
        Bs[ty][tx] = (col < N) ? Bm[(size_t)(k0 + ty) * N + col] : 0.f;
        __syncthreads();
#pragma unroll
        for (int kk = 0; kk < 16; kk++) acc += As[ty][kk] * Bs[kk][tx];
        __syncthreads();
    }
    if (row < M && col < N) C[(size_t)row * N + col] = acc;
}

// Same but fp16 output
__global__ void k_gemm_h(const float* __restrict__ A, const float* __restrict__ Bm,
                         __half* __restrict__ C, int M, int N) {
    __shared__ float As[16][17], Bs[16][17];
    int tx = threadIdx.x, ty = threadIdx.y;
    int row = blockIdx.y * 16 + ty, col = blockIdx.x * 16 + tx;
    float acc = 0.f;
    for (int k0 = 0; k0 < DX; k0 += 16) {
        As[ty][tx] = (row < M) ? A[row * DX + k0 + tx] : 0.f;
        Bs[ty][tx] = (col < N) ? Bm[(size_t)(k0 + ty) * N + col] : 0.f;
        __syncthreads();
#pragma unroll
        for (int kk = 0; kk < 16; kk++) acc += As[ty][kk] * Bs[kk][tx];
        __syncthreads();
    }
    if (row < M && col < N) C[(size_t)row * N + col] = __float2half(acc);
}

// e_m[n] = b_c[n] + sum_{j<m} (G_j * db)[n],  m = 0..16, db = b_A+b_K+b_B
__global__ void k_bias(const float* __restrict__ bA, const float* __restrict__ bK,
                       const float* __restrict__ bB, const float* __restrict__ bCy,
                       const float* __restrict__ bCz) {
    __shared__ float db[DX];
    int tid = threadIdx.x;
    if (tid < DX) db[tid] = bA[tid] + bK[tid] + bB[tid];
    __syncthreads();
    if (tid < DON) {
        float acc = (tid < DY) ? bCy[tid] : bCz[tid - DY];
        g_e[tid] = acc;
        for (int j = 0; j < KTAP; j++) {
            const float* g = g_G + ((size_t)j * DON + tid) * DX;
            float s = 0.f;
#pragma unroll 8
            for (int i = 0; i < DX; i++) s += g[i] * db[i];
            acc += s;
            g_e[(j + 1) * DON + tid] = acc;
        }
    }
}

// ---------------- main conv kernel ----------------
#define TT      128
#define VROWS   (TT + KTAP)          // 144 input rows (with left halo)
#define VPITCH  400                  // 192 fp16 (384B) + 16B pad
#define WPITCH  208                  // 96 fp16 (192B) + 16B pad
#define WSTAGE  (DON * WPITCH)       // 39936
#define SM_W0   (VROWS * VPITCH)     // 57600
#define SMEM_TOTAL (SM_W0 + 2 * WSTAGE)   // 137472

__device__ __forceinline__ void ldmx4(uint32_t a, uint32_t& r0, uint32_t& r1,
                                      uint32_t& r2, uint32_t& r3) {
    asm volatile("ldmatrix.sync.aligned.m8n8.x4.shared.b16 {%0,%1,%2,%3},[%4];"
                 : "=r"(r0), "=r"(r1), "=r"(r2), "=r"(r3) : "r"(a));
}
__device__ __forceinline__ void mma16816(float* c, const uint32_t* a, uint32_t b0, uint32_t b1) {
    asm volatile("mma.sync.aligned.m16n8k16.row.col.f32.f16.f16.f32 "
                 "{%0,%1,%2,%3},{%4,%5,%6,%7},{%8,%9},{%0,%1,%2,%3};"
                 : "+f"(c[0]), "+f"(c[1]), "+f"(c[2]), "+f"(c[3])
                 : "r"(a[0]), "r"(a[1]), "r"(a[2]), "r"(a[3]), "r"(b0), "r"(b1));
}
#define CPA16(d, s) asm volatile("cp.async.ca.shared.global [%0],[%1],16;" :: "r"(d), "l"(s))
#define CP_COMMIT() asm volatile("cp.async.commit_group;")
#define CP_WAIT1()  asm volatile("cp.async.wait_group 1;")

// stage = 2*j + kc : load R_j[:, kc*96 .. +96) into smem buffer at byte offset wb
__device__ __forceinline__ void issue_wstage(uint32_t wb, int stage, int tid) {
    int j = stage >> 1, kc = stage & 1;
    const __half* src0 = g_R + (size_t)j * DON * DIN + kc * 96;
#pragma unroll
    for (int i = 0; i < 9; i++) {           // 192 rows * 12 chunks(16B) = 2304 = 256*9
        int q = tid + i * 256;
        int n = q / 12, m = q % 12;
        CPA16(wb + n * WPITCH + m * 16, src0 + (size_t)n * DIN + m * 8);
    }
}

__global__ void __launch_bounds__(256, 1)
k_conv(const float* __restrict__ y, const float* __restrict__ u,
       float* __restrict__ yout, float* __restrict__ zout) {
    extern __shared__ char smem[];
    const uint32_t sbase = (uint32_t)__cvta_generic_to_shared(smem);
    const int tid  = threadIdx.x;
    const int lane = tid & 31, wid = tid >> 5;
    const int warpM = wid >> 2;     // 0..1 : 64 timesteps each
    const int warpN = wid & 3;      // 0..3 : 48 output channels each
    const int b  = blockIdx.y;
    const int t0 = blockIdx.x * TT;

    // prefetch weight stages 0,1
    issue_wstage(sbase + SM_W0, 0, tid);          CP_COMMIT();
    issue_wstage(sbase + SM_W0 + WSTAGE, 1, tid); CP_COMMIT();

    // input tile [144 x 192] fp32 -> fp16, zero left halo (t<0)
    {
        char* vb = smem;
#pragma unroll 4
        for (int i = 0; i < 108; i++) {           // 144*192 = 27648 = 256*108
            int q = tid + i * 256;
            int s = q / DIN, c = q % DIN;
            int tm = t0 - KTAP + s;
            float val = 0.f;
            if (tm >= 0)
                val = (c < DY) ? y[((size_t)b * T_ + tm) * DY + c]
                               : u[((size_t)b * T_ + tm) * DU + (c - DY)];
            *(__half*)(vb + s * VPITCH + c * 2) = __float2half(val);
        }
    }

    float acc[4][6][4];
#pragma unroll
    for (int a = 0; a < 4; a++)
#pragma unroll
        for (int q = 0; q < 6; q++)
#pragma unroll
            for (int c = 0; c < 4; c++) acc[a][q][c] = 0.f;

    // 32 stages = (tap j, k-chunk kc); weights double-buffered
#pragma unroll 1
    for (int st = 0; st < 2 * KTAP; st++) {
        CP_WAIT1();
        __syncthreads();
        const int j = st >> 1, kc = st & 1;
        const uint32_t wb = sbase + SM_W0 + (st & 1) * WSTAGE;
        const int shift = (KTAP - 1) - j;         // A-row shift for this tap

#pragma unroll
        for (int ks = 0; ks < 6; ks++) {          // 96-ch chunk = 6 k16 steps
            const int c = kc * 96 + ks * 16;

            // A fragments: 4 m16 tiles
            uint32_t af[4][4];
#pragma unroll
            for (int a = 0; a < 4; a++) {
                int mr = warpM * 64 + a * 16 + shift;
                uint32_t addr = sbase + (uint32_t)(mr + (lane & 15)) * VPITCH
                              + (uint32_t)(c + ((lane >> 4) << 3)) * 2;
                ldmx4(addr, af[a][0], af[a][1], af[a][2], af[a][3]);
            }
            // B fragments: 6 n8 tiles via 3 x4 loads
            uint32_t bf[6][2];
#pragma unroll
            for (int np = 0; np < 3; np++) {
                int nb  = warpN * 48 + np * 16;
                int sub = lane >> 3;              // 0..3
                int nrow = nb + ((sub >> 1) << 3) + (lane & 7);
                int kcol = ks * 16 + ((sub & 1) << 3);
                uint32_t addr = wb + (uint32_t)nrow * WPITCH + (uint32_t)kcol * 2;
                ldmx4(addr, bf[np*2][0], bf[np*2][1], bf[np*2+1][0], bf[np*2+1][1]);
            }
#pragma unroll
            for (int a = 0; a < 4; a++)
#pragma unroll
                for (int q = 0; q < 6; q++)
                    mma16816(acc[a][q], af[a], bf[q][0], bf[q][1]);
        }
        __syncthreads();
        if (st + 2 < 2 * KTAP)
            issue_wstage(sbase + SM_W0 + (st & 1) * WSTAGE, st + 2, tid);
        CP_COMMIT();                               // always commit (group accounting)
    }

    // epilogue: add bias table, write split outputs
    const int rbase = warpM * 64, nbase = warpN * 48;
#pragma unroll
    for (int a = 0; a < 4; a++) {
        int rr = rbase + a * 16 + (lane >> 2);
#pragma unroll
        for (int cc = 0; cc < 2; cc++) {
            int r = rr + cc * 8;
            int t = t0 + r;
            int m = t < KTAP ? t : KTAP;
            const float* ev = g_e + m * DON;
#pragma unroll
            for (int q = 0; q < 6; q++) {
                int n  = nbase + q * 8 + (lane & 3) * 2;
                float v0 = acc[a][q][cc * 2 + 0] + ev[n];
                float v1 = acc[a][q][cc * 2 + 1] + ev[n + 1];
                if (n < DY) {
                    size_t o = ((size_t)b * T_ + t) * DY + n;
                    yout[o] = v0; yout[o + 1] = v1;
                } else {
                    size_t o = ((size_t)b * T_ + t) * DU + (n - DY);
                    zout[o] = v0; zout[o + 1] = v1;
                }
            }
        }
    }
}

// ---------------- launch ----------------
extern "C" void kernel_launch(void* const* d_in, const int* in_sizes, int n_in,
                              void* d_out, int out_size) {
    const float* y   = (const float*)d_in[0];
    const float* u   = (const float*)d_in[1];
    const float* W_A = (const float*)d_in[2];
    const float* b_A = (const float*)d_in[3];
    const float* W_K = (const float*)d_in[4];
    const float* b_K = (const float*)d_in[5];
    const float* W_B = (const float*)d_in[6];
    const float* b_B = (const float*)d_in[7];
    const float* W_Cy= (const float*)d_in[8];
    const float* b_Cy= (const float*)d_in[9];
    const float* W_Cz= (const float*)d_in[10];
    const float* b_Cz= (const float*)d_in[11];
    float* yout = (float*)d_out;
    float* zout = (float*)d_out + (size_t)B_ * T_ * DY;

    void *pG = nullptr, *pWd = nullptr, *pR = nullptr;
    cudaGetSymbolAddress(&pG,  g_G);
    cudaGetSymbolAddress(&pWd, g_Wd);
    cudaGetSymbolAddress(&pR,  g_R);
    float*  G  = (float*)pG;
    float*  Wd = (float*)pWd;
    __half* R  = (__half*)pR;

    // G_0 = C ; G_{j+1} = G_j * W_A
    k_copy_g0<<<(DON * DX + 255) / 256, 256>>>(W_Cy, W_Cz, G);
    for (int j = 0; j < KTAP - 1; j++)
        k_gemm<<<dim3(DX / 16, DON / 16), dim3(16, 16)>>>(
            G + (size_t)j * DON * DX, W_A, G + (size_t)(j + 1) * DON * DX, DON, DX);

    // W_d = [W_K | W_B] ; R_j = G_j * W_d (fp16)
    k_asm_wd<<<(DX * DIN + 255) / 256, 256>>>(W_K, W_B, Wd);
    for (int j = 0; j < KTAP; j++)
        k_gemm_h<<<dim3(DIN / 16, DON / 16), dim3(16, 16)>>>(
            G + (size_t)j * DON * DX, Wd, R + (size_t)j * DON * DIN, DON, DIN);

    // bias table
    k_bias<<<1, 256>>>(b_A, b_K, b_B, b_Cy, b_Cz);

    // main conv
    cudaFuncSetAttribute(k_conv, cudaFuncAttributeMaxDynamicSharedMemorySize, SMEM_TOTAL);
    k_conv<<<dim3(T_ / TT, B_), 256, SMEM_TOTAL>>>(y, u, yout, zout);
}